// round 1
// baseline (speedup 1.0000x reference)
#include <cuda_runtime.h>
#include <cuda_bf16.h>

#define FULLMASK 0xffffffffu

struct C2 { float x, y; };

__device__ __forceinline__ C2 cmul(C2 a, C2 b) {
    return C2{a.x * b.x - a.y * b.y, a.x * b.y + a.y * b.x};
}
__device__ __forceinline__ C2 cadd(C2 a, C2 b) { return C2{a.x + b.x, a.y + b.y}; }
__device__ __forceinline__ C2 shxor(C2 v, int m) {
    v.x = __shfl_xor_sync(FULLMASK, v.x, m);
    v.y = __shfl_xor_sync(FULLMASK, v.y, m);
    return v;
}

// ---- single-qubit Ry (real rotation [[c,-s],[s,c]]) on qubit Q ----
template <int Q>
__device__ __forceinline__ void applyRy(C2 s[8], float c, float sn, int lane) {
    if constexpr (Q < 3) {
        constexpr int m = 1 << Q;
#pragma unroll
        for (int j = 0; j < 8; j++) {
            if (!(j & m)) {
                C2 a = s[j], b = s[j | m];
                s[j]     = C2{c * a.x - sn * b.x, c * a.y - sn * b.y};
                s[j | m] = C2{sn * a.x + c * b.x, sn * a.y + c * b.y};
            }
        }
    } else {
        constexpr int lb = 1 << (Q - 3);
        bool hi = (lane & lb) != 0;
        float sgn = hi ? sn : -sn;   // low: c*own - s*other ; high: c*own + s*other
#pragma unroll
        for (int j = 0; j < 8; j++) {
            C2 o = shxor(s[j], lb);
            s[j] = C2{c * s[j].x + sgn * o.x, c * s[j].y + sgn * o.y};
        }
    }
}

// ---- general single-qubit complex gate on qubit Q ----
template <int Q>
__device__ __forceinline__ void applyU(C2 s[8], C2 u00, C2 u01, C2 u10, C2 u11, int lane) {
    if constexpr (Q < 3) {
        constexpr int m = 1 << Q;
#pragma unroll
        for (int j = 0; j < 8; j++) {
            if (!(j & m)) {
                C2 a = s[j], b = s[j | m];
                s[j]     = cadd(cmul(u00, a), cmul(u01, b));
                s[j | m] = cadd(cmul(u10, a), cmul(u11, b));
            }
        }
    } else {
        constexpr int lb = 1 << (Q - 3);
        bool hi = (lane & lb) != 0;
        C2 ua = hi ? u10 : u00;
        C2 ub = hi ? u11 : u01;
#pragma unroll
        for (int j = 0; j < 8; j++) {
            C2 o = shxor(s[j], lb);
            C2 a = hi ? o : s[j];
            C2 b = hi ? s[j] : o;
            s[j] = cadd(cmul(ua, a), cmul(ub, b));
        }
    }
}

// ---- controlled general gate: control Cq, target Tq ----
template <int Cq, int Tq>
__device__ __forceinline__ void applyCU(C2 s[8], C2 u00, C2 u01, C2 u10, C2 u11, int lane) {
    bool laneCtrl = (Cq >= 3) ? (((lane >> (Cq - 3)) & 1) != 0) : false;
    if constexpr (Tq < 3) {
        constexpr int tm = 1 << Tq;
#pragma unroll
        for (int j = 0; j < 8; j++) {
            if (!(j & tm)) {
                bool ctrl = (Cq < 3) ? (((j >> Cq) & 1) != 0) : laneCtrl;
                if (ctrl) {
                    C2 a = s[j], b = s[j | tm];
                    s[j]      = cadd(cmul(u00, a), cmul(u01, b));
                    s[j | tm] = cadd(cmul(u10, a), cmul(u11, b));
                }
            }
        }
    } else {
        constexpr int lb = 1 << (Tq - 3);
        bool hi = (lane & lb) != 0;
        C2 ua = hi ? u10 : u00;
        C2 ub = hi ? u11 : u01;
#pragma unroll
        for (int j = 0; j < 8; j++) {
            C2 o = shxor(s[j], lb);   // all lanes must shuffle
            bool ctrl = (Cq < 3) ? (((j >> Cq) & 1) != 0) : laneCtrl;
            C2 a = hi ? o : s[j];
            C2 b = hi ? s[j] : o;
            C2 r = cadd(cmul(ua, a), cmul(ub, b));
            if (ctrl) s[j] = r;
        }
    }
}

// ---- CNOT: control Cq, target Tq (swap target pair where control=1) ----
template <int Cq, int Tq>
__device__ __forceinline__ void cnot(C2 s[8], int lane) {
    bool laneCtrl = (Cq >= 3) ? (((lane >> (Cq - 3)) & 1) != 0) : false;
    if constexpr (Tq < 3) {
        constexpr int tm = 1 << Tq;
#pragma unroll
        for (int j = 0; j < 8; j++) {
            if (!(j & tm)) {
                bool ctrl = (Cq < 3) ? (((j >> Cq) & 1) != 0) : laneCtrl;
                if (ctrl) {
                    C2 t = s[j];
                    s[j] = s[j | tm];
                    s[j | tm] = t;
                }
            }
        }
    } else {
        constexpr int lb = 1 << (Tq - 3);
#pragma unroll
        for (int j = 0; j < 8; j++) {
            C2 o = shxor(s[j], lb);
            bool ctrl = (Cq < 3) ? (((j >> Cq) & 1) != 0) : laneCtrl;
            if (ctrl) s[j] = o;
        }
    }
}

__global__ __launch_bounds__(256) void qcnn_kernel(
    const float* __restrict__ theta, const float* __restrict__ phi,
    const float* __restrict__ angles_x, const float* __restrict__ angles_y,
    const float* __restrict__ angles_z,
    const float* __restrict__ u3_x, const float* __restrict__ u3_y,
    const float* __restrict__ u3_z,
    const float* __restrict__ W1, const float* __restrict__ b1,
    const float* __restrict__ W2, const float* __restrict__ b2,
    float* __restrict__ out, int B)
{
    // ---- shared: batch-invariant gate matrices + MLP weights ----
    __shared__ C2 shRot[3 * 10 * 4];   // [branch][gate][4]
    __shared__ C2 shU3[3 * 6 * 4];     // [branch][gate][4]
    __shared__ float shW1[72], shB1[12], shW2[12];
    __shared__ float shB2;

    int tid = threadIdx.x;
    if (tid < 30) {
        int b = tid / 10, i = tid % 10;
        const float* ang = (b == 0) ? angles_x : (b == 1) ? angles_y : angles_z;
        float t = ang[i];
        float sn, c;
        sincosf(0.5f * t, &sn, &c);
        C2 u00, u01, u10, u11;
        if (b == 0) {        // rx
            u00 = C2{c, 0.f}; u01 = C2{0.f, -sn}; u10 = C2{0.f, -sn}; u11 = C2{c, 0.f};
        } else if (b == 1) { // ry
            u00 = C2{c, 0.f}; u01 = C2{-sn, 0.f}; u10 = C2{sn, 0.f}; u11 = C2{c, 0.f};
        } else {             // rz: diag(e^{-it/2}, e^{it/2})
            u00 = C2{c, -sn}; u01 = C2{0.f, 0.f}; u10 = C2{0.f, 0.f}; u11 = C2{c, sn};
        }
        shRot[tid * 4 + 0] = u00; shRot[tid * 4 + 1] = u01;
        shRot[tid * 4 + 2] = u10; shRot[tid * 4 + 3] = u11;
    }
    if (tid >= 32 && tid < 50) {
        int k = tid - 32;
        int b = k / 6, i = k % 6;
        const float* up = ((b == 0) ? u3_x : (b == 1) ? u3_y : u3_z) + i * 3;
        float th = up[0], ph = up[1], lm = up[2];
        float sn, c;    sincosf(0.5f * th, &sn, &c);
        float sl, cl;   sincosf(lm, &sl, &cl);
        float sp, cp;   sincosf(ph, &sp, &cp);
        float spl, cpl; sincosf(ph + lm, &spl, &cpl);
        shU3[k * 4 + 0] = C2{c, 0.f};
        shU3[k * 4 + 1] = C2{-cl * sn, -sl * sn};
        shU3[k * 4 + 2] = C2{cp * sn, sp * sn};
        shU3[k * 4 + 3] = C2{cpl * c, spl * c};
    }
    if (tid >= 64 && tid < 136)  shW1[tid - 64] = W1[tid - 64];
    if (tid >= 136 && tid < 148) shB1[tid - 136] = b1[tid - 136];
    if (tid >= 148 && tid < 160) shW2[tid - 148] = W2[tid - 148];
    if (tid == 160) shB2 = b2[0];
    __syncthreads();

    int warp = tid >> 5;
    int lane = tid & 31;
    int batch = blockIdx.x * 8 + warp;
    if (batch >= B) return;

    float th = theta[batch];
    float ph = phi[batch];

    // ---- init state |0...0>; amp index = (lane<<3)|j; qubit w <-> index bit w ----
    C2 s[8];
#pragma unroll
    for (int j = 0; j < 8; j++) s[j] = C2{0.f, 0.f};
    if (lane == 0) s[0] = C2{1.f, 0.f};

    float sy, cy;
    sincosf(0.5f * th, &sy, &cy);

    // Combined per-cycle Rz diagonal: amp *= cis(ph * (popcount(idx) - 4)).
    // Precompute per-j phase factors once (cycle-invariant).
    C2 c1; sincosf(ph, &c1.y, &c1.x);
    C2 c2 = cmul(c1, c1);
    C2 c3 = cmul(c2, c1);
    C2 cl0; sincosf(ph * (float)(__popc(lane) - 4), &cl0.y, &cl0.x);
    C2 pj[8];
    pj[0] = cl0;
    pj[1] = cmul(cl0, c1); pj[2] = pj[1]; pj[4] = pj[1];
    pj[3] = cmul(cl0, c2); pj[5] = pj[3]; pj[6] = pj[3];
    pj[7] = cmul(cl0, c3);

#pragma unroll 1
    for (int cyc = 0; cyc < 4; cyc++) {
        applyRy<0>(s, cy, sy, lane);
        applyRy<1>(s, cy, sy, lane);
        applyRy<2>(s, cy, sy, lane);
        applyRy<3>(s, cy, sy, lane);
        applyRy<4>(s, cy, sy, lane);
        applyRy<5>(s, cy, sy, lane);
        applyRy<6>(s, cy, sy, lane);
        applyRy<7>(s, cy, sy, lane);
#pragma unroll
        for (int j = 0; j < 8; j++) s[j] = cmul(s[j], pj[j]);
        cnot<0, 1>(s, lane);
        cnot<1, 2>(s, lane);
        cnot<2, 3>(s, lane);
        cnot<3, 4>(s, lane);
        cnot<4, 5>(s, lane);
        cnot<5, 6>(s, lane);
        cnot<6, 7>(s, lane);
        cnot<7, 0>(s, lane);
    }

    // ---- save psi0 ----
    C2 p0[8];
#pragma unroll
    for (int j = 0; j < 8; j++) p0[j] = s[j];

    float feats[6];

#pragma unroll
    for (int b = 0; b < 3; b++) {
#pragma unroll
        for (int j = 0; j < 8; j++) s[j] = p0[j];

        const C2* RM = &shRot[b * 40];
        const C2* UM = &shU3[b * 24];

#define CUG(i, Cq, Tq)                                                         \
        {                                                                      \
            C2 g0 = RM[(i) * 4 + 0], g1 = RM[(i) * 4 + 1];                     \
            C2 g2 = RM[(i) * 4 + 2], g3 = RM[(i) * 4 + 3];                     \
            applyCU<Cq, Tq>(s, g0, g1, g2, g3, lane);                          \
        }
#define U3G(i, W)                                                              \
        {                                                                      \
            C2 g0 = UM[(i) * 4 + 0], g1 = UM[(i) * 4 + 1];                     \
            C2 g2 = UM[(i) * 4 + 2], g3 = UM[(i) * 4 + 3];                     \
            applyU<W>(s, g0, g1, g2, g3, lane);                                \
        }

        // PAIRS_A
        CUG(0, 0, 1) CUG(1, 2, 3) CUG(2, 4, 5) CUG(3, 6, 7)
        CUG(4, 1, 2) CUG(5, 3, 4) CUG(6, 5, 6)
        // u3 on wires 1,3,5,7
        U3G(0, 1) U3G(1, 3) U3G(2, 5) U3G(3, 7)
        // PAIRS_B
        CUG(7, 1, 3) CUG(8, 5, 7) CUG(9, 3, 5)
        // u3 on wires 3,7
        U3G(4, 3) U3G(5, 7)
#undef CUG
#undef U3G

        // expz(3) and expz(7): qubit3 = lane bit0, qubit7 = lane bit4
        float pt = 0.f;
#pragma unroll
        for (int j = 0; j < 8; j++) pt += s[j].x * s[j].x + s[j].y * s[j].y;
        float e3 = (lane & 1) ? -pt : pt;
        float e7 = (lane & 16) ? -pt : pt;
#pragma unroll
        for (int o = 16; o > 0; o >>= 1) {
            e3 += __shfl_xor_sync(FULLMASK, e3, o);
            e7 += __shfl_xor_sync(FULLMASK, e7, o);
        }
        feats[2 * b]     = e3;
        feats[2 * b + 1] = e7;
    }

    // ---- MLP (lane 0 only) ----
    if (lane == 0) {
        float h[12];
#pragma unroll
        for (int k = 0; k < 12; k++) {
            float a = shB1[k];
#pragma unroll
            for (int f = 0; f < 6; f++) a += shW1[k * 6 + f] * feats[f];
            h[k] = tanhf(a);
        }
        float o = shB2;
#pragma unroll
        for (int k = 0; k < 12; k++) o += shW2[k] * h[k];
        out[batch] = 1.f / (1.f + expf(-o));
    }
}

extern "C" void kernel_launch(void* const* d_in, const int* in_sizes, int n_in,
                              void* d_out, int out_size) {
    const float* theta    = (const float*)d_in[0];
    const float* phi      = (const float*)d_in[1];
    const float* angles_x = (const float*)d_in[2];
    const float* angles_y = (const float*)d_in[3];
    const float* angles_z = (const float*)d_in[4];
    const float* u3_x     = (const float*)d_in[5];
    const float* u3_y     = (const float*)d_in[6];
    const float* u3_z     = (const float*)d_in[7];
    const float* W1       = (const float*)d_in[8];
    const float* b1       = (const float*)d_in[9];
    const float* W2       = (const float*)d_in[10];
    const float* b2       = (const float*)d_in[11];
    float* out = (float*)d_out;

    int B = in_sizes[0];
    int blocks = (B + 7) / 8;
    qcnn_kernel<<<blocks, 256>>>(theta, phi, angles_x, angles_y, angles_z,
                                 u3_x, u3_y, u3_z, W1, b1, W2, b2, out, B);
}

// round 2
// speedup vs baseline: 1.2399x; 1.2399x over previous
#include <cuda_runtime.h>
#include <cuda_bf16.h>

#define FULLMASK 0xffffffffu

// Qubit -> amplitude-index-bit mapping (chosen to minimize shuffle gates):
//   q3->bit0, q5->bit1, q7->bit2  (register bits: j index 0..7)
//   q0->bit3, q1->bit4, q2->bit5, q4->bit6, q6->bit7  (lane bits)
// amp index = (lane << 3) | j

struct C2 { float x, y; };

__device__ __forceinline__ C2 cmul(C2 a, C2 b) {
    return C2{a.x * b.x - a.y * b.y, a.x * b.y + a.y * b.x};
}
__device__ __forceinline__ C2 cadd(C2 a, C2 b) { return C2{a.x + b.x, a.y + b.y}; }
__device__ __forceinline__ C2 shxor(C2 v, int m) {
    v.x = __shfl_xor_sync(FULLMASK, v.x, m);
    v.y = __shfl_xor_sync(FULLMASK, v.y, m);
    return v;
}

// ---- single-qubit Ry on index-bit Tb ----
template <int Tb>
__device__ __forceinline__ void applyRy(C2 s[8], float c, float sn, int lane) {
    if constexpr (Tb < 3) {
        constexpr int m = 1 << Tb;
#pragma unroll
        for (int j = 0; j < 8; j++) {
            if (!(j & m)) {
                C2 a = s[j], b = s[j | m];
                s[j]     = C2{c * a.x - sn * b.x, c * a.y - sn * b.y};
                s[j | m] = C2{sn * a.x + c * b.x, sn * a.y + c * b.y};
            }
        }
    } else {
        constexpr int lb = 1 << (Tb - 3);
        bool hi = (lane & lb) != 0;
        float sgn = hi ? sn : -sn;
#pragma unroll
        for (int j = 0; j < 8; j++) {
            C2 o = shxor(s[j], lb);
            s[j] = C2{c * s[j].x + sgn * o.x, c * s[j].y + sgn * o.y};
        }
    }
}

// ---- general single-qubit gate on index-bit Tb ----
template <int Tb>
__device__ __forceinline__ void applyU(C2 s[8], C2 u00, C2 u01, C2 u10, C2 u11, int lane) {
    if constexpr (Tb < 3) {
        constexpr int m = 1 << Tb;
#pragma unroll
        for (int j = 0; j < 8; j++) {
            if (!(j & m)) {
                C2 a = s[j], b = s[j | m];
                s[j]     = cadd(cmul(u00, a), cmul(u01, b));
                s[j | m] = cadd(cmul(u10, a), cmul(u11, b));
            }
        }
    } else {
        constexpr int lb = 1 << (Tb - 3);
        bool hi = (lane & lb) != 0;
        C2 ua = hi ? u10 : u00;
        C2 ub = hi ? u11 : u01;
#pragma unroll
        for (int j = 0; j < 8; j++) {
            C2 o = shxor(s[j], lb);
            C2 a = hi ? o : s[j];
            C2 b = hi ? s[j] : o;
            s[j] = cadd(cmul(ua, a), cmul(ub, b));
        }
    }
}

// ---- controlled gate: control index-bit Cb, target index-bit Tb ----
template <int Cb, int Tb>
__device__ __forceinline__ void applyCU(C2 s[8], C2 u00, C2 u01, C2 u10, C2 u11, int lane) {
    bool laneCtrl = (Cb >= 3) ? (((lane >> (Cb - 3)) & 1) != 0) : false;
    if constexpr (Tb < 3) {
        constexpr int tm = 1 << Tb;
#pragma unroll
        for (int j = 0; j < 8; j++) {
            if (!(j & tm)) {
                bool ctrl = (Cb < 3) ? (((j >> Cb) & 1) != 0) : laneCtrl;
                if (ctrl) {
                    C2 a = s[j], b = s[j | tm];
                    s[j]      = cadd(cmul(u00, a), cmul(u01, b));
                    s[j | tm] = cadd(cmul(u10, a), cmul(u11, b));
                }
            }
        }
    } else {
        constexpr int lb = 1 << (Tb - 3);
        bool hi = (lane & lb) != 0;
        C2 ua = hi ? u10 : u00;
        C2 ub = hi ? u11 : u01;
#pragma unroll
        for (int j = 0; j < 8; j++) {
            C2 o = shxor(s[j], lb);
            bool ctrl = (Cb < 3) ? (((j >> Cb) & 1) != 0) : laneCtrl;
            C2 a = hi ? o : s[j];
            C2 b = hi ? s[j] : o;
            C2 r = cadd(cmul(ua, a), cmul(ub, b));
            if (ctrl) s[j] = r;
        }
    }
}

// ---- CNOT: control index-bit Cb, target index-bit Tb ----
template <int Cb, int Tb>
__device__ __forceinline__ void cnot(C2 s[8], int lane) {
    bool laneCtrl = (Cb >= 3) ? (((lane >> (Cb - 3)) & 1) != 0) : false;
    if constexpr (Tb < 3) {
        constexpr int tm = 1 << Tb;
#pragma unroll
        for (int j = 0; j < 8; j++) {
            if (!(j & tm)) {
                bool ctrl = (Cb < 3) ? (((j >> Cb) & 1) != 0) : laneCtrl;
                if (ctrl) {
                    C2 t = s[j];
                    s[j] = s[j | tm];
                    s[j | tm] = t;
                }
            }
        }
    } else {
        constexpr int lb = 1 << (Tb - 3);
#pragma unroll
        for (int j = 0; j < 8; j++) {
            C2 o = shxor(s[j], lb);
            bool ctrl = (Cb < 3) ? (((j >> Cb) & 1) != 0) : laneCtrl;
            if (ctrl) s[j] = o;
        }
    }
}

__global__ __launch_bounds__(256) void qcnn_kernel(
    const float* __restrict__ theta, const float* __restrict__ phi,
    const float* __restrict__ angles_x, const float* __restrict__ angles_y,
    const float* __restrict__ angles_z,
    const float* __restrict__ u3_x, const float* __restrict__ u3_y,
    const float* __restrict__ u3_z,
    const float* __restrict__ W1, const float* __restrict__ b1,
    const float* __restrict__ W2, const float* __restrict__ b2,
    float* __restrict__ out, int B)
{
    __shared__ C2 shRot[3 * 10 * 4];
    __shared__ C2 shU3[3 * 6 * 4];
    __shared__ float shW1[72], shB1[12], shW2[12];
    __shared__ float shB2;

    int tid = threadIdx.x;
    if (tid < 30) {
        int b = tid / 10, i = tid % 10;
        const float* ang = (b == 0) ? angles_x : (b == 1) ? angles_y : angles_z;
        float t = ang[i];
        float sn, c;
        sincosf(0.5f * t, &sn, &c);
        C2 u00, u01, u10, u11;
        if (b == 0) {        // rx
            u00 = C2{c, 0.f}; u01 = C2{0.f, -sn}; u10 = C2{0.f, -sn}; u11 = C2{c, 0.f};
        } else if (b == 1) { // ry
            u00 = C2{c, 0.f}; u01 = C2{-sn, 0.f}; u10 = C2{sn, 0.f}; u11 = C2{c, 0.f};
        } else {             // rz
            u00 = C2{c, -sn}; u01 = C2{0.f, 0.f}; u10 = C2{0.f, 0.f}; u11 = C2{c, sn};
        }
        shRot[tid * 4 + 0] = u00; shRot[tid * 4 + 1] = u01;
        shRot[tid * 4 + 2] = u10; shRot[tid * 4 + 3] = u11;
    }
    if (tid >= 32 && tid < 50) {
        int k = tid - 32;
        int b = k / 6, i = k % 6;
        const float* up = ((b == 0) ? u3_x : (b == 1) ? u3_y : u3_z) + i * 3;
        float th = up[0], ph = up[1], lm = up[2];
        float sn, c;    sincosf(0.5f * th, &sn, &c);
        float sl, cl;   sincosf(lm, &sl, &cl);
        float sp, cp;   sincosf(ph, &sp, &cp);
        float spl, cpl; sincosf(ph + lm, &spl, &cpl);
        shU3[k * 4 + 0] = C2{c, 0.f};
        shU3[k * 4 + 1] = C2{-cl * sn, -sl * sn};
        shU3[k * 4 + 2] = C2{cp * sn, sp * sn};
        shU3[k * 4 + 3] = C2{cpl * c, spl * c};
    }
    if (tid >= 64 && tid < 136)  shW1[tid - 64] = W1[tid - 64];
    if (tid >= 136 && tid < 148) shB1[tid - 136] = b1[tid - 136];
    if (tid >= 148 && tid < 160) shW2[tid - 148] = W2[tid - 148];
    if (tid == 160) shB2 = b2[0];
    __syncthreads();

    int warp = tid >> 5;
    int lane = tid & 31;
    int batch = blockIdx.x * 8 + warp;
    if (batch >= B) return;

    float th = theta[batch];
    float ph = phi[batch];

    float sy, cy;
    sincosf(0.5f * th, &sy, &cy);

    // Rz-layer combined diagonal: amp *= cis(ph * (popcount(idx) - 4))
    C2 c1; sincosf(ph, &c1.y, &c1.x);
    C2 c2 = cmul(c1, c1);
    C2 c3 = cmul(c2, c1);
    C2 cl0; sincosf(ph * (float)(__popc(lane) - 4), &cl0.y, &cl0.x);
    C2 pj[8];
    pj[0] = cl0;
    pj[1] = cmul(cl0, c1); pj[2] = pj[1]; pj[4] = pj[1];
    pj[3] = cmul(cl0, c2); pj[5] = pj[3]; pj[6] = pj[3];
    pj[7] = cmul(cl0, c3);

    // ---- cycle 1: product state closed form: amp = cy^(8-p) sy^p * cis(ph(p-4)) ----
    C2 s[8];
    {
        float base = 1.f;
#pragma unroll
        for (int k = 0; k < 5; k++) base *= ((lane >> k) & 1) ? sy : cy;
        float f0 = cy * cy * cy;
        float f1 = cy * cy * sy;
        float f2 = cy * sy * sy;
        float f3 = sy * sy * sy;
        float fj[8] = {f0, f1, f1, f2, f1, f2, f2, f3};
#pragma unroll
        for (int j = 0; j < 8; j++) {
            float w = base * fj[j];
            s[j] = C2{pj[j].x * w, pj[j].y * w};
        }
    }
    // CNOT ring of cycle 1 (qubit pairs mapped to bits)
    cnot<3, 4>(s, lane);  // (0,1)
    cnot<4, 5>(s, lane);  // (1,2)
    cnot<5, 0>(s, lane);  // (2,3)
    cnot<0, 6>(s, lane);  // (3,4)
    cnot<6, 1>(s, lane);  // (4,5)
    cnot<1, 7>(s, lane);  // (5,6)
    cnot<7, 2>(s, lane);  // (6,7)
    cnot<2, 3>(s, lane);  // (7,0)

    // ---- cycles 2..4 ----
#pragma unroll 1
    for (int cyc = 0; cyc < 3; cyc++) {
        applyRy<0>(s, cy, sy, lane);
        applyRy<1>(s, cy, sy, lane);
        applyRy<2>(s, cy, sy, lane);
        applyRy<3>(s, cy, sy, lane);
        applyRy<4>(s, cy, sy, lane);
        applyRy<5>(s, cy, sy, lane);
        applyRy<6>(s, cy, sy, lane);
        applyRy<7>(s, cy, sy, lane);
#pragma unroll
        for (int j = 0; j < 8; j++) s[j] = cmul(s[j], pj[j]);
        cnot<3, 4>(s, lane);
        cnot<4, 5>(s, lane);
        cnot<5, 0>(s, lane);
        cnot<0, 6>(s, lane);
        cnot<6, 1>(s, lane);
        cnot<1, 7>(s, lane);
        cnot<7, 2>(s, lane);
        cnot<2, 3>(s, lane);
    }

    // ---- save psi0 ----
    C2 p0[8];
#pragma unroll
    for (int j = 0; j < 8; j++) p0[j] = s[j];

    float feats[6];

#pragma unroll
    for (int b = 0; b < 3; b++) {
#pragma unroll
        for (int j = 0; j < 8; j++) s[j] = p0[j];

        const C2* RM = &shRot[b * 40];
        const C2* UM = &shU3[b * 24];

#define CUG(i, Cb, Tb)                                                         \
        {                                                                      \
            C2 g0 = RM[(i) * 4 + 0], g1 = RM[(i) * 4 + 1];                     \
            C2 g2 = RM[(i) * 4 + 2], g3 = RM[(i) * 4 + 3];                     \
            applyCU<Cb, Tb>(s, g0, g1, g2, g3, lane);                          \
        }
#define U3G(i, Tb)                                                             \
        {                                                                      \
            C2 g0 = UM[(i) * 4 + 0], g1 = UM[(i) * 4 + 1];                     \
            C2 g2 = UM[(i) * 4 + 2], g3 = UM[(i) * 4 + 3];                     \
            applyU<Tb>(s, g0, g1, g2, g3, lane);                               \
        }

        // PAIRS_A (qubit pairs -> bit pairs)
        CUG(0, 3, 4)  // (0,1)
        CUG(1, 5, 0)  // (2,3)
        CUG(2, 6, 1)  // (4,5)
        CUG(3, 7, 2)  // (6,7)
        CUG(4, 4, 5)  // (1,2)
        CUG(5, 0, 6)  // (3,4)
        CUG(6, 1, 7)  // (5,6)
        // u3 on wires 1,3,5,7 -> bits 4,0,1,2
        U3G(0, 4) U3G(1, 0) U3G(2, 1) U3G(3, 2)
        // PAIRS_B
        CUG(7, 4, 0)  // (1,3)
        CUG(8, 1, 2)  // (5,7)
        CUG(9, 0, 1)  // (3,5)
        // u3 on wires 3,7 -> bits 0,2
        U3G(4, 0) U3G(5, 2)
#undef CUG
#undef U3G

        // expz(q3)=bit0, expz(q7)=bit2 : signs live in j now
        float q[8];
#pragma unroll
        for (int j = 0; j < 8; j++) q[j] = s[j].x * s[j].x + s[j].y * s[j].y;
        float e3 = (q[0] - q[1]) + (q[2] - q[3]) + (q[4] - q[5]) + (q[6] - q[7]);
        float e7 = (q[0] + q[1]) + (q[2] + q[3]) - (q[4] + q[5]) - (q[6] + q[7]);
#pragma unroll
        for (int o = 16; o > 0; o >>= 1) {
            e3 += __shfl_xor_sync(FULLMASK, e3, o);
            e7 += __shfl_xor_sync(FULLMASK, e7, o);
        }
        feats[2 * b]     = e3;
        feats[2 * b + 1] = e7;
    }

    // ---- MLP (lane 0 only) ----
    if (lane == 0) {
        float h[12];
#pragma unroll
        for (int k = 0; k < 12; k++) {
            float a = shB1[k];
#pragma unroll
            for (int f = 0; f < 6; f++) a += shW1[k * 6 + f] * feats[f];
            h[k] = tanhf(a);
        }
        float o = shB2;
#pragma unroll
        for (int k = 0; k < 12; k++) o += shW2[k] * h[k];
        out[batch] = 1.f / (1.f + expf(-o));
    }
}

extern "C" void kernel_launch(void* const* d_in, const int* in_sizes, int n_in,
                              void* d_out, int out_size) {
    const float* theta    = (const float*)d_in[0];
    const float* phi      = (const float*)d_in[1];
    const float* angles_x = (const float*)d_in[2];
    const float* angles_y = (const float*)d_in[3];
    const float* angles_z = (const float*)d_in[4];
    const float* u3_x     = (const float*)d_in[5];
    const float* u3_y     = (const float*)d_in[6];
    const float* u3_z     = (const float*)d_in[7];
    const float* W1       = (const float*)d_in[8];
    const float* b1       = (const float*)d_in[9];
    const float* W2       = (const float*)d_in[10];
    const float* b2       = (const float*)d_in[11];
    float* out = (float*)d_out;

    int B = in_sizes[0];
    int blocks = (B + 7) / 8;
    qcnn_kernel<<<blocks, 256>>>(theta, phi, angles_x, angles_y, angles_z,
                                 u3_x, u3_y, u3_z, W1, b1, W2, b2, out, B);
}

// round 3
// speedup vs baseline: 1.5897x; 1.2822x over previous
#include <cuda_runtime.h>
#include <cuda_bf16.h>

#define FULLMASK 0xffffffffu

// Qubit -> amplitude-index-bit mapping:
//   q3->bit0, q5->bit1, q7->bit2  (register bits: j index 0..7)
//   q0->bit3, q1->bit4, q2->bit5, q4->bit6, q6->bit7  (lane bits 0..4)
// amp index = (lane << 3) | j

struct C2 { float x, y; };

__device__ __forceinline__ C2 cmul(C2 a, C2 b) {
    return C2{a.x * b.x - a.y * b.y, a.x * b.y + a.y * b.x};
}
__device__ __forceinline__ C2 cadd(C2 a, C2 b) { return C2{a.x + b.x, a.y + b.y}; }
__device__ __forceinline__ C2 shxor(C2 v, int m) {
    v.x = __shfl_xor_sync(FULLMASK, v.x, m);
    v.y = __shfl_xor_sync(FULLMASK, v.y, m);
    return v;
}

// ---- single-qubit Ry on index-bit Tb ----
template <int Tb>
__device__ __forceinline__ void applyRy(C2 s[8], float c, float sn, int lane) {
    if constexpr (Tb < 3) {
        constexpr int m = 1 << Tb;
#pragma unroll
        for (int j = 0; j < 8; j++) {
            if (!(j & m)) {
                C2 a = s[j], b = s[j | m];
                s[j]     = C2{c * a.x - sn * b.x, c * a.y - sn * b.y};
                s[j | m] = C2{sn * a.x + c * b.x, sn * a.y + c * b.y};
            }
        }
    } else {
        constexpr int lb = 1 << (Tb - 3);
        bool hi = (lane & lb) != 0;
        float sgn = hi ? sn : -sn;
#pragma unroll
        for (int j = 0; j < 8; j++) {
            C2 o = shxor(s[j], lb);
            s[j] = C2{c * s[j].x + sgn * o.x, c * s[j].y + sgn * o.y};
        }
    }
}

// ---- general single-qubit gate on index-bit Tb ----
template <int Tb>
__device__ __forceinline__ void applyU(C2 s[8], C2 u00, C2 u01, C2 u10, C2 u11, int lane) {
    if constexpr (Tb < 3) {
        constexpr int m = 1 << Tb;
#pragma unroll
        for (int j = 0; j < 8; j++) {
            if (!(j & m)) {
                C2 a = s[j], b = s[j | m];
                s[j]     = cadd(cmul(u00, a), cmul(u01, b));
                s[j | m] = cadd(cmul(u10, a), cmul(u11, b));
            }
        }
    } else {
        constexpr int lb = 1 << (Tb - 3);
        bool hi = (lane & lb) != 0;
        C2 ua = hi ? u10 : u00;
        C2 ub = hi ? u11 : u01;
#pragma unroll
        for (int j = 0; j < 8; j++) {
            C2 o = shxor(s[j], lb);
            C2 a = hi ? o : s[j];
            C2 b = hi ? s[j] : o;
            s[j] = cadd(cmul(ua, a), cmul(ub, b));
        }
    }
}

// ---- controlled rotation: K=0 rx, K=1 ry, K=2 rz; control bit Cb, target bit Tb ----
// c = cos(t/2), sn = sin(t/2)
template <int K, int Cb, int Tb>
__device__ __forceinline__ void applyCR(C2 s[8], float c, float sn, int lane) {
    if constexpr (K == 2) {
        // CRz: diagonal — no amplitude mixing, no shuffles ever.
        if constexpr (Cb < 3) {
#pragma unroll
            for (int j = 0; j < 8; j++) {
                if (j & (1 << Cb)) {
                    bool tb = (Tb < 3) ? (((j >> Tb) & 1) != 0)
                                       : (((lane >> (Tb - 3)) & 1) != 0);
                    float ss = tb ? sn : -sn;
                    C2 v = s[j];
                    s[j] = C2{c * v.x - ss * v.y, c * v.y + ss * v.x};
                }
            }
        } else {
            bool lc = ((lane >> (Cb - 3)) & 1) != 0;
#pragma unroll
            for (int j = 0; j < 8; j++) {
                bool tb = (Tb < 3) ? (((j >> Tb) & 1) != 0)
                                   : (((lane >> (Tb - 3)) & 1) != 0);
                float ss = tb ? sn : -sn;
                C2 v = s[j];
                C2 r = C2{c * v.x - ss * v.y, c * v.y + ss * v.x};
                if (lc) s[j] = r;
            }
        }
    } else if constexpr (Tb < 3) {
        constexpr int tm = 1 << Tb;
        bool lc = (Cb >= 3) ? (((lane >> (Cb - 3)) & 1) != 0) : false;
#pragma unroll
        for (int j = 0; j < 8; j++) {
            if (!(j & tm)) {
                bool ctrl = (Cb < 3) ? (((j >> Cb) & 1) != 0) : lc;
                if (ctrl) {
                    C2 a = s[j], b = s[j | tm];
                    if constexpr (K == 0) {   // rx: [[c,-is],[-is,c]]
                        s[j]      = C2{c * a.x + sn * b.y, c * a.y - sn * b.x};
                        s[j | tm] = C2{c * b.x + sn * a.y, c * b.y - sn * a.x};
                    } else {                  // ry: [[c,-s],[s,c]]
                        s[j]      = C2{c * a.x - sn * b.x, c * a.y - sn * b.y};
                        s[j | tm] = C2{sn * a.x + c * b.x, sn * a.y + c * b.y};
                    }
                }
            }
        }
    } else {
        constexpr int lb = 1 << (Tb - 3);
        bool hi = (lane & lb) != 0;
        if constexpr (Cb < 3) {
            // register control: only j with ctrl=1 participate; unconditional there
#pragma unroll
            for (int j = 0; j < 8; j++) {
                if (j & (1 << Cb)) {
                    C2 o = shxor(s[j], lb);
                    if constexpr (K == 0) {
                        s[j] = C2{c * s[j].x + sn * o.y, c * s[j].y - sn * o.x};
                    } else {
                        float sg = hi ? sn : -sn;
                        s[j] = C2{c * s[j].x + sg * o.x, c * s[j].y + sg * o.y};
                    }
                }
            }
        } else {
            bool lc = ((lane >> (Cb - 3)) & 1) != 0;
            float sg = hi ? sn : -sn;
#pragma unroll
            for (int j = 0; j < 8; j++) {
                C2 o = shxor(s[j], lb);
                C2 r;
                if constexpr (K == 0) r = C2{c * s[j].x + sn * o.y, c * s[j].y - sn * o.x};
                else                  r = C2{c * s[j].x + sg * o.x, c * s[j].y + sg * o.y};
                if (lc) s[j] = r;
            }
        }
    }
}

// ---- CNOT: control bit Cb, target bit Tb ----
template <int Cb, int Tb>
__device__ __forceinline__ void cnot(C2 s[8], int lane) {
    if constexpr (Tb < 3) {
        constexpr int tm = 1 << Tb;
        bool lc = (Cb >= 3) ? (((lane >> (Cb - 3)) & 1) != 0) : false;
#pragma unroll
        for (int j = 0; j < 8; j++) {
            if (!(j & tm)) {
                bool ctrl = (Cb < 3) ? (((j >> Cb) & 1) != 0) : lc;
                if (ctrl) { C2 t = s[j]; s[j] = s[j | tm]; s[j | tm] = t; }
            }
        }
    } else {
        constexpr int lb = 1 << (Tb - 3);
        if constexpr (Cb < 3) {
            // register control: shuffle only the 4 j's with ctrl=1, unconditional swap
#pragma unroll
            for (int j = 0; j < 8; j++)
                if (j & (1 << Cb)) s[j] = shxor(s[j], lb);
        } else {
            bool lc = ((lane >> (Cb - 3)) & 1) != 0;
#pragma unroll
            for (int j = 0; j < 8; j++) {
                C2 o = shxor(s[j], lb);
                if (lc) s[j] = o;
            }
        }
    }
}

// fused cnot<3,4>; cnot<4,5> — pure lane permutation, one gather shuffle
__device__ __forceinline__ void ring_head(C2 s[8], int lane) {
    int src = lane ^ (((lane >> 1) & 1) << 2) ^ ((lane & 1) << 1);
#pragma unroll
    for (int j = 0; j < 8; j++) {
        s[j].x = __shfl_sync(FULLMASK, s[j].x, src);
        s[j].y = __shfl_sync(FULLMASK, s[j].y, src);
    }
}

__device__ __forceinline__ void ring_layer(C2 s[8], int lane) {
    ring_head(s, lane);   // (q0,q1), (q1,q2)
    cnot<5, 0>(s, lane);  // (q2,q3)
    cnot<0, 6>(s, lane);  // (q3,q4)
    cnot<6, 1>(s, lane);  // (q4,q5)
    cnot<1, 7>(s, lane);  // (q5,q6)
    cnot<7, 2>(s, lane);  // (q6,q7)
    cnot<2, 3>(s, lane);  // (q7,q0)
}

template <int K>
__device__ __forceinline__ void runBranch(C2 s[8], const float2* CS, const C2* UM,
                                          int lane, float& e3, float& e7) {
#define CR(i, Cb, Tb) applyCR<K, Cb, Tb>(s, CS[i].x, CS[i].y, lane);
#define U3G(i, Tb) applyU<Tb>(s, UM[(i)*4+0], UM[(i)*4+1], UM[(i)*4+2], UM[(i)*4+3], lane);
    // PAIRS_A
    CR(0, 3, 4)  // (0,1)
    CR(1, 5, 0)  // (2,3)
    CR(2, 6, 1)  // (4,5)
    CR(3, 7, 2)  // (6,7)
    CR(4, 4, 5)  // (1,2)
    CR(5, 0, 6)  // (3,4)
    CR(6, 1, 7)  // (5,6)
    // u3 on wires 1,3,5,7 -> bits 4,0,1,2
    U3G(0, 4) U3G(1, 0) U3G(2, 1) U3G(3, 2)
    // PAIRS_B
    CR(7, 4, 0)  // (1,3)
    CR(8, 1, 2)  // (5,7)
    CR(9, 0, 1)  // (3,5)
    // u3 on wires 3,7 -> bits 0,2
    U3G(4, 0) U3G(5, 2)
#undef CR
#undef U3G

    float q[8];
#pragma unroll
    for (int j = 0; j < 8; j++) q[j] = s[j].x * s[j].x + s[j].y * s[j].y;
    e3 = (q[0] - q[1]) + (q[2] - q[3]) + (q[4] - q[5]) + (q[6] - q[7]);
    e7 = (q[0] + q[1]) + (q[2] + q[3]) - (q[4] + q[5]) - (q[6] + q[7]);
#pragma unroll
    for (int o = 16; o > 0; o >>= 1) {
        e3 += __shfl_xor_sync(FULLMASK, e3, o);
        e7 += __shfl_xor_sync(FULLMASK, e7, o);
    }
}

__global__ __launch_bounds__(256) void qcnn_kernel(
    const float* __restrict__ theta, const float* __restrict__ phi,
    const float* __restrict__ angles_x, const float* __restrict__ angles_y,
    const float* __restrict__ angles_z,
    const float* __restrict__ u3_x, const float* __restrict__ u3_y,
    const float* __restrict__ u3_z,
    const float* __restrict__ W1, const float* __restrict__ b1,
    const float* __restrict__ W2, const float* __restrict__ b2,
    float* __restrict__ out, int B)
{
    __shared__ float2 shCS[30];        // [branch][gate] = (cos(t/2), sin(t/2))
    __shared__ C2 shU3[3 * 6 * 4];
    __shared__ float shW1[72], shB1[12], shW2[12];
    __shared__ float shB2;

    int tid = threadIdx.x;
    if (tid < 30) {
        int b = tid / 10, i = tid % 10;
        const float* ang = (b == 0) ? angles_x : (b == 1) ? angles_y : angles_z;
        float sn, c;
        sincosf(0.5f * ang[i], &sn, &c);
        shCS[tid] = make_float2(c, sn);
    }
    if (tid >= 32 && tid < 50) {
        int k = tid - 32;
        int b = k / 6, i = k % 6;
        const float* up = ((b == 0) ? u3_x : (b == 1) ? u3_y : u3_z) + i * 3;
        float th = up[0], ph = up[1], lm = up[2];
        float sn, c;    sincosf(0.5f * th, &sn, &c);
        float sl, cl;   sincosf(lm, &sl, &cl);
        float sp, cp;   sincosf(ph, &sp, &cp);
        float spl, cpl; sincosf(ph + lm, &spl, &cpl);
        shU3[k * 4 + 0] = C2{c, 0.f};
        shU3[k * 4 + 1] = C2{-cl * sn, -sl * sn};
        shU3[k * 4 + 2] = C2{cp * sn, sp * sn};
        shU3[k * 4 + 3] = C2{cpl * c, spl * c};
    }
    if (tid >= 64 && tid < 136)  shW1[tid - 64] = W1[tid - 64];
    if (tid >= 136 && tid < 148) shB1[tid - 136] = b1[tid - 136];
    if (tid >= 148 && tid < 160) shW2[tid - 148] = W2[tid - 148];
    if (tid == 160) shB2 = b2[0];
    __syncthreads();

    int warp = tid >> 5;
    int lane = tid & 31;
    int batch = blockIdx.x * 8 + warp;
    if (batch >= B) return;

    float th = theta[batch];
    float ph = phi[batch];

    float sy, cy;
    sincosf(0.5f * th, &sy, &cy);

    // Rz-layer combined diagonal: amp *= cis(ph * (popcount(idx) - 4))
    C2 c1; sincosf(ph, &c1.y, &c1.x);
    C2 c2 = cmul(c1, c1);
    C2 c3 = cmul(c2, c1);
    C2 cl0; sincosf(ph * (float)(__popc(lane) - 4), &cl0.y, &cl0.x);
    C2 pj[8];
    pj[0] = cl0;
    pj[1] = cmul(cl0, c1); pj[2] = pj[1]; pj[4] = pj[1];
    pj[3] = cmul(cl0, c2); pj[5] = pj[3]; pj[6] = pj[3];
    pj[7] = cmul(cl0, c3);

    // ---- cycle 1: closed form product state ----
    C2 s[8];
    {
        float base = 1.f;
#pragma unroll
        for (int k = 0; k < 5; k++) base *= ((lane >> k) & 1) ? sy : cy;
        float f0 = cy * cy * cy;
        float f1 = cy * cy * sy;
        float f2 = cy * sy * sy;
        float f3 = sy * sy * sy;
        float fj[8] = {f0, f1, f1, f2, f1, f2, f2, f3};
#pragma unroll
        for (int j = 0; j < 8; j++) {
            float w = base * fj[j];
            s[j] = C2{pj[j].x * w, pj[j].y * w};
        }
    }
    ring_layer(s, lane);

    // ---- cycles 2..4 ----
#pragma unroll 1
    for (int cyc = 0; cyc < 3; cyc++) {
        applyRy<0>(s, cy, sy, lane);
        applyRy<1>(s, cy, sy, lane);
        applyRy<2>(s, cy, sy, lane);
        applyRy<3>(s, cy, sy, lane);
        applyRy<4>(s, cy, sy, lane);
        applyRy<5>(s, cy, sy, lane);
        applyRy<6>(s, cy, sy, lane);
        applyRy<7>(s, cy, sy, lane);
#pragma unroll
        for (int j = 0; j < 8; j++) s[j] = cmul(s[j], pj[j]);
        ring_layer(s, lane);
    }

    // ---- save psi0 ----
    C2 p0[8];
#pragma unroll
    for (int j = 0; j < 8; j++) p0[j] = s[j];

    float feats[6];

    // branch x
    runBranch<0>(s, &shCS[0], &shU3[0], lane, feats[0], feats[1]);
    // branch y
#pragma unroll
    for (int j = 0; j < 8; j++) s[j] = p0[j];
    runBranch<1>(s, &shCS[10], &shU3[24], lane, feats[2], feats[3]);
    // branch z
#pragma unroll
    for (int j = 0; j < 8; j++) s[j] = p0[j];
    runBranch<2>(s, &shCS[20], &shU3[48], lane, feats[4], feats[5]);

    // ---- MLP (lane 0 only) ----
    if (lane == 0) {
        float h[12];
#pragma unroll
        for (int k = 0; k < 12; k++) {
            float a = shB1[k];
#pragma unroll
            for (int f = 0; f < 6; f++) a += shW1[k * 6 + f] * feats[f];
            h[k] = tanhf(a);
        }
        float o = shB2;
#pragma unroll
        for (int k = 0; k < 12; k++) o += shW2[k] * h[k];
        out[batch] = 1.f / (1.f + expf(-o));
    }
}

extern "C" void kernel_launch(void* const* d_in, const int* in_sizes, int n_in,
                              void* d_out, int out_size) {
    const float* theta    = (const float*)d_in[0];
    const float* phi      = (const float*)d_in[1];
    const float* angles_x = (const float*)d_in[2];
    const float* angles_y = (const float*)d_in[3];
    const float* angles_z = (const float*)d_in[4];
    const float* u3_x     = (const float*)d_in[5];
    const float* u3_y     = (const float*)d_in[6];
    const float* u3_z     = (const float*)d_in[7];
    const float* W1       = (const float*)d_in[8];
    const float* b1       = (const float*)d_in[9];
    const float* W2       = (const float*)d_in[10];
    const float* b2       = (const float*)d_in[11];
    float* out = (float*)d_out;

    int B = in_sizes[0];
    int blocks = (B + 7) / 8;
    qcnn_kernel<<<blocks, 256>>>(theta, phi, angles_x, angles_y, angles_z,
                                 u3_x, u3_y, u3_z, W1, b1, W2, b2, out, B);
}

// round 4
// speedup vs baseline: 1.7909x; 1.1265x over previous
#include <cuda_runtime.h>
#include <cuda_bf16.h>

#define FULLMASK 0xffffffffu
typedef unsigned long long u64;

// Qubit -> amplitude-index-bit mapping:
//   q3->bit0, q5->bit1, q7->bit2  (register bits: j index 0..7)
//   q0->bit3(L0), q1->bit4(L1), q2->bit5(L2), q4->bit6(L3), q6->bit7(L4)
// amp index = (lane << 3) | j ; amplitude = packed (re, im) in one 64-bit pair

__device__ __forceinline__ u64 pk(float lo, float hi) {
    u64 r; asm("mov.b64 %0, {%1, %2};" : "=l"(r) : "f"(lo), "f"(hi)); return r;
}
__device__ __forceinline__ void upk(u64 v, float& x, float& y) {
    asm("mov.b64 {%0, %1}, %2;" : "=f"(x), "=f"(y) : "l"(v));
}
__device__ __forceinline__ u64 f2mul(u64 a, u64 b) {
    u64 r; asm("mul.rn.f32x2 %0, %1, %2;" : "=l"(r) : "l"(a), "l"(b)); return r;
}
__device__ __forceinline__ u64 f2fma(u64 a, u64 b, u64 c) {
    u64 r; asm("fma.rn.f32x2 %0, %1, %2, %3;" : "=l"(r) : "l"(a), "l"(b), "l"(c)); return r;
}
__device__ __forceinline__ u64 swp(u64 v) { float x, y; upk(v, x, y); return pk(y, x); }
__device__ __forceinline__ u64 shx64(u64 v, int m) { return __shfl_xor_sync(FULLMASK, v, m); }
// shuffle returning the partner amplitude with halves swapped: (o.im, o.re)
__device__ __forceinline__ u64 shxswp(u64 v, int m) {
    float x, y; upk(v, x, y);
    float sx = __shfl_xor_sync(FULLMASK, x, m);
    float sy = __shfl_xor_sync(FULLMASK, y, m);
    return pk(sy, sx);
}

// ---- Ry on index-bit Tb: cc=(c,c), pp=(s,s), nn=(-s,-s) ----
template <int Tb>
__device__ __forceinline__ void applyRy(u64 s[8], u64 cc, u64 pp, u64 nn, int lane) {
    if constexpr (Tb < 3) {
        constexpr int m = 1 << Tb;
#pragma unroll
        for (int j = 0; j < 8; j++) {
            if (!(j & m)) {
                u64 a = s[j], b = s[j | m];
                s[j]     = f2fma(cc, a, f2mul(nn, b));
                s[j | m] = f2fma(cc, b, f2mul(pp, a));
            }
        }
    } else {
        constexpr int lb = 1 << (Tb - 3);
        u64 sg = (lane & lb) ? pp : nn;
#pragma unroll
        for (int j = 0; j < 8; j++) {
            u64 o = shx64(s[j], lb);
            s[j] = f2fma(cc, s[j], f2mul(sg, o));
        }
    }
}

// ---- controlled rotation: K=0 rx, K=1 ry, K=2 rz ----
// G[0]=(c,c) G[1]=(s,s) G[2]=(-s,-s) G[3]=(s,-s) G[4]=(-s,s)
template <int K, int Cb, int Tb>
__device__ __forceinline__ void applyCR(u64 s[8], const u64* __restrict__ G, int lane) {
    u64 cc = G[0];
    if constexpr (K == 2) {
        // CRz diagonal: v' = fma(cc, v, mul(f, swap(v))), f = (s,-s) for t=0, (-s,s) for t=1
        u64 pm = G[3], mp = G[4];
        bool laneT = (Tb >= 3) ? (((lane >> (Tb - 3)) & 1) != 0) : false;
        if constexpr (Cb < 3) {
#pragma unroll
            for (int j = 0; j < 8; j++) {
                if (j & (1 << Cb)) {
                    bool tb = (Tb < 3) ? (((j >> Tb) & 1) != 0) : laneT;
                    u64 f = tb ? mp : pm;
                    s[j] = f2fma(cc, s[j], f2mul(f, swp(s[j])));
                }
            }
        } else {
            bool lc = ((lane >> (Cb - 3)) & 1) != 0;
#pragma unroll
            for (int j = 0; j < 8; j++) {
                bool tb = (Tb < 3) ? (((j >> Tb) & 1) != 0) : laneT;
                u64 f = tb ? mp : pm;
                u64 r = f2fma(cc, s[j], f2mul(f, swp(s[j])));
                if (lc) s[j] = r;
            }
        }
    } else if constexpr (Tb < 3) {
        constexpr int tm = 1 << Tb;
        bool lc = (Cb >= 3) ? (((lane >> (Cb - 3)) & 1) != 0) : false;
#pragma unroll
        for (int j = 0; j < 8; j++) {
            if (!(j & tm) && (Cb >= 3 || ((j >> Cb) & 1))) {
                u64 a = s[j], b = s[j | tm], na, nb;
                if constexpr (K == 0) {   // rx
                    u64 pm = G[3];
                    na = f2fma(cc, a, f2mul(pm, swp(b)));
                    nb = f2fma(cc, b, f2mul(pm, swp(a)));
                } else {                  // ry
                    na = f2fma(cc, a, f2mul(G[2], b));
                    nb = f2fma(cc, b, f2mul(G[1], a));
                }
                if constexpr (Cb < 3) { s[j] = na; s[j | tm] = nb; }
                else { if (lc) { s[j] = na; s[j | tm] = nb; } }
            }
        }
    } else {
        constexpr int lb = 1 << (Tb - 3);
        u64 sg = (lane & lb) ? G[1] : G[2];
        if constexpr (Cb < 3) {
#pragma unroll
            for (int j = 0; j < 8; j++) {
                if (j & (1 << Cb)) {
                    if constexpr (K == 0) {
                        u64 os = shxswp(s[j], lb);
                        s[j] = f2fma(cc, s[j], f2mul(G[3], os));
                    } else {
                        u64 o = shx64(s[j], lb);
                        s[j] = f2fma(cc, s[j], f2mul(sg, o));
                    }
                }
            }
        } else {
            bool lc = ((lane >> (Cb - 3)) & 1) != 0;
#pragma unroll
            for (int j = 0; j < 8; j++) {
                u64 r;
                if constexpr (K == 0) r = f2fma(cc, s[j], f2mul(G[3], shxswp(s[j], lb)));
                else                  r = f2fma(cc, s[j], f2mul(sg, shx64(s[j], lb)));
                if (lc) s[j] = r;
            }
        }
    }
}

// ---- general u3 gate; U: u00r,u00i,u01r,u01i,u10r,u10i,u11r,u11i (uXr=(re,re), uXi=(-im,im)) ----
// u00 is always real -> its imaginary term is omitted in the pair path.
template <int Tb>
__device__ __forceinline__ void applyU3(u64 s[8], const u64* __restrict__ U, int lane) {
    if constexpr (Tb < 3) {
        constexpr int m = 1 << Tb;
#pragma unroll
        for (int j = 0; j < 8; j++) {
            if (!(j & m)) {
                u64 a = s[j], b = s[j | m];
                u64 as = swp(a), bs = swp(b);
                s[j]     = f2fma(U[0], a, f2fma(U[2], b, f2mul(U[3], bs)));
                s[j | m] = f2fma(U[4], a, f2fma(U[5], as, f2fma(U[6], b, f2mul(U[7], bs))));
            }
        }
    } else {
        constexpr int lb = 1 << (Tb - 3);
        bool hi = (lane & lb) != 0;
        u64 Ar = hi ? U[6] : U[0];
        u64 Ai = hi ? U[7] : U[1];
        u64 Br = hi ? U[4] : U[2];
        u64 Bi = hi ? U[5] : U[3];
#pragma unroll
        for (int j = 0; j < 8; j++) {
            float x, y; upk(s[j], x, y);
            float ox = __shfl_xor_sync(FULLMASK, x, lb);
            float oy = __shfl_xor_sync(FULLMASK, y, lb);
            u64 o = pk(ox, oy), os = pk(oy, ox), ss2 = pk(y, x);
            s[j] = f2fma(Ar, s[j], f2fma(Ai, ss2, f2fma(Br, o, f2mul(Bi, os))));
        }
    }
}

// ---- CNOT ----
template <int Cb, int Tb>
__device__ __forceinline__ void cnot(u64 s[8], int lane) {
    if constexpr (Tb < 3) {
        constexpr int tm = 1 << Tb;
        bool lc = (Cb >= 3) ? (((lane >> (Cb - 3)) & 1) != 0) : false;
#pragma unroll
        for (int j = 0; j < 8; j++) {
            if (!(j & tm)) {
                bool ctrl = (Cb < 3) ? (((j >> Cb) & 1) != 0) : lc;
                if (ctrl) { u64 t = s[j]; s[j] = s[j | tm]; s[j | tm] = t; }
            }
        }
    } else {
        constexpr int lb = 1 << (Tb - 3);
        if constexpr (Cb < 3) {
#pragma unroll
            for (int j = 0; j < 8; j++)
                if (j & (1 << Cb)) s[j] = shx64(s[j], lb);
        } else {
            bool lc = ((lane >> (Cb - 3)) & 1) != 0;
#pragma unroll
            for (int j = 0; j < 8; j++) {
                u64 o = shx64(s[j], lb);
                if (lc) s[j] = o;
            }
        }
    }
}

// fused cnot<3,4>; cnot<4,5> — pure lane permutation, one gather shuffle
__device__ __forceinline__ void ring_head(u64 s[8], int lane) {
    int src = lane ^ (((lane >> 1) & 1) << 2) ^ ((lane & 1) << 1);
#pragma unroll
    for (int j = 0; j < 8; j++) s[j] = __shfl_sync(FULLMASK, s[j], src);
}

__device__ __forceinline__ void ring_layer(u64 s[8], int lane) {
    ring_head(s, lane);   // (q0,q1), (q1,q2)
    cnot<5, 0>(s, lane);  // (q2,q3)
    cnot<0, 6>(s, lane);  // (q3,q4)
    cnot<6, 1>(s, lane);  // (q4,q5)
    cnot<1, 7>(s, lane);  // (q5,q6)
    cnot<7, 2>(s, lane);  // (q6,q7)
    cnot<2, 3>(s, lane);  // (q7,q0)
}

template <int K>
__device__ __forceinline__ void runBranch(u64 s[8], const u64* __restrict__ CR,
                                          const u64* __restrict__ UM,
                                          int lane, float& e3, float& e7) {
#define CRG(i, Cb, Tb) applyCR<K, Cb, Tb>(s, CR + (i) * 5, lane);
#define U3G(i, Tb) applyU3<Tb>(s, UM + (i) * 8, lane);
    // PAIRS_A
    CRG(0, 3, 4)  // (0,1)
    CRG(1, 5, 0)  // (2,3)
    CRG(2, 6, 1)  // (4,5)
    CRG(3, 7, 2)  // (6,7)
    CRG(4, 4, 5)  // (1,2)
    CRG(5, 0, 6)  // (3,4)
    CRG(6, 1, 7)  // (5,6)
    // u3 on wires 1,3,5,7 -> bits 4,0,1,2
    U3G(0, 4) U3G(1, 0) U3G(2, 1) U3G(3, 2)
    // PAIRS_B
    CRG(7, 4, 0)  // (1,3)
    CRG(8, 1, 2)  // (5,7)
    CRG(9, 0, 1)  // (3,5)
    // u3 on wires 3,7 -> bits 0,2
    U3G(4, 0) U3G(5, 2)
#undef CRG
#undef U3G

    float q[8];
#pragma unroll
    for (int j = 0; j < 8; j++) {
        float x, y; upk(s[j], x, y);
        q[j] = x * x + y * y;
    }
    e3 = (q[0] - q[1]) + (q[2] - q[3]) + (q[4] - q[5]) + (q[6] - q[7]);
    e7 = (q[0] + q[1]) + (q[2] + q[3]) - (q[4] + q[5]) - (q[6] + q[7]);
#pragma unroll
    for (int o = 16; o > 0; o >>= 1) {
        e3 += __shfl_xor_sync(FULLMASK, e3, o);
        e7 += __shfl_xor_sync(FULLMASK, e7, o);
    }
}

__global__ __launch_bounds__(256) void qcnn_kernel(
    const float* __restrict__ theta, const float* __restrict__ phi,
    const float* __restrict__ angles_x, const float* __restrict__ angles_y,
    const float* __restrict__ angles_z,
    const float* __restrict__ u3_x, const float* __restrict__ u3_y,
    const float* __restrict__ u3_z,
    const float* __restrict__ W1, const float* __restrict__ b1,
    const float* __restrict__ W2, const float* __restrict__ b2,
    float* __restrict__ out, int B)
{
    __shared__ u64 shCR[3 * 10 * 5];   // packed (c,c),(s,s),(-s,-s),(s,-s),(-s,s)
    __shared__ u64 shU3[3 * 6 * 8];    // packed uXr/uXi
    __shared__ float shW1[72], shB1[12], shW2[12];
    __shared__ float shB2;

    int tid = threadIdx.x;
    if (tid < 30) {
        int b = tid / 10, i = tid % 10;
        const float* ang = (b == 0) ? angles_x : (b == 1) ? angles_y : angles_z;
        float sn, c;
        sincosf(0.5f * ang[i], &sn, &c);
        u64* g = &shCR[tid * 5];
        g[0] = pk(c, c);
        g[1] = pk(sn, sn);
        g[2] = pk(-sn, -sn);
        g[3] = pk(sn, -sn);
        g[4] = pk(-sn, sn);
    }
    if (tid >= 32 && tid < 50) {
        int k = tid - 32;
        int b = k / 6, i = k % 6;
        const float* up = ((b == 0) ? u3_x : (b == 1) ? u3_y : u3_z) + i * 3;
        float th = up[0], ph = up[1], lm = up[2];
        float sn, c;    sincosf(0.5f * th, &sn, &c);
        float sl, cl;   sincosf(lm, &sl, &cl);
        float sp, cp;   sincosf(ph, &sp, &cp);
        float spl, cpl; sincosf(ph + lm, &spl, &cpl);
        // u00=(c,0) u01=(-cl*sn,-sl*sn) u10=(cp*sn,sp*sn) u11=(cpl*c,spl*c)
        u64* g = &shU3[k * 8];
        g[0] = pk(c, c);                 g[1] = pk(0.f, 0.f);
        g[2] = pk(-cl * sn, -cl * sn);   g[3] = pk(sl * sn, -sl * sn);
        g[4] = pk(cp * sn, cp * sn);     g[5] = pk(-sp * sn, sp * sn);
        g[6] = pk(cpl * c, cpl * c);     g[7] = pk(-spl * c, spl * c);
    }
    if (tid >= 64 && tid < 136)  shW1[tid - 64] = W1[tid - 64];
    if (tid >= 136 && tid < 148) shB1[tid - 136] = b1[tid - 136];
    if (tid >= 148 && tid < 160) shW2[tid - 148] = W2[tid - 148];
    if (tid == 160) shB2 = b2[0];
    __syncthreads();

    int warp = tid >> 5;
    int lane = tid & 31;
    int batch = blockIdx.x * 8 + warp;
    if (batch >= B) return;

    float th = theta[batch];
    float ph = phi[batch];

    float sy, cy;
    sincosf(0.5f * th, &sy, &cy);
    u64 cc = pk(cy, cy), pp = pk(sy, sy), nn = pk(-sy, -sy);

    // Rz-layer combined diagonal: amp *= cis(ph * (popcount(idx) - 4))
    // Per-j factor depends only on d = popc(j) (0..3): pj[d] = cl0 * cis(ph)^d
    float c1x, c1y; sincosf(ph, &c1y, &c1x);
    float cl0x, cl0y; sincosf(ph * (float)(__popc(lane) - 4), &cl0y, &cl0x);
    float px[4], py[4];
    px[0] = cl0x; py[0] = cl0y;
    px[1] = px[0] * c1x - py[0] * c1y; py[1] = px[0] * c1y + py[0] * c1x;
    px[2] = px[1] * c1x - py[1] * c1y; py[2] = px[1] * c1y + py[1] * c1x;
    px[3] = px[2] * c1x - py[2] * c1y; py[3] = px[2] * c1y + py[2] * c1x;
    const int POPC[8] = {0, 1, 1, 2, 1, 2, 2, 3};

    // ---- cycle 1: closed form product state ----
    u64 s[8];
    {
        float base = 1.f;
#pragma unroll
        for (int k = 0; k < 5; k++) base *= ((lane >> k) & 1) ? sy : cy;
        float f0 = cy * cy * cy;
        float f1 = cy * cy * sy;
        float f2 = cy * sy * sy;
        float f3 = sy * sy * sy;
        float fj[8] = {f0, f1, f1, f2, f1, f2, f2, f3};
#pragma unroll
        for (int j = 0; j < 8; j++) {
            float w = base * fj[j];
            int d = POPC[j];
            s[j] = pk(px[d] * w, py[d] * w);
        }
    }
    ring_layer(s, lane);

    // ---- cycles 2..4 ----
#pragma unroll 1
    for (int cyc = 0; cyc < 3; cyc++) {
        applyRy<0>(s, cc, pp, nn, lane);
        applyRy<1>(s, cc, pp, nn, lane);
        applyRy<2>(s, cc, pp, nn, lane);
        applyRy<3>(s, cc, pp, nn, lane);
        applyRy<4>(s, cc, pp, nn, lane);
        applyRy<5>(s, cc, pp, nn, lane);
        applyRy<6>(s, cc, pp, nn, lane);
        applyRy<7>(s, cc, pp, nn, lane);
        // phase multiply (scalar complex mul by per-j constant)
#pragma unroll
        for (int j = 0; j < 8; j++) {
            float x, y; upk(s[j], x, y);
            int d = POPC[j];
            s[j] = pk(px[d] * x - py[d] * y, px[d] * y + py[d] * x);
        }
        ring_layer(s, lane);
    }

    // ---- save psi0 ----
    u64 p0[8];
#pragma unroll
    for (int j = 0; j < 8; j++) p0[j] = s[j];

    float feats[6];

    runBranch<0>(s, &shCR[0],   &shU3[0],  lane, feats[0], feats[1]);
#pragma unroll
    for (int j = 0; j < 8; j++) s[j] = p0[j];
    runBranch<1>(s, &shCR[50],  &shU3[48], lane, feats[2], feats[3]);
#pragma unroll
    for (int j = 0; j < 8; j++) s[j] = p0[j];
    runBranch<2>(s, &shCR[100], &shU3[96], lane, feats[4], feats[5]);

    // ---- MLP (lane 0 only) ----
    if (lane == 0) {
        float h[12];
#pragma unroll
        for (int k = 0; k < 12; k++) {
            float a = shB1[k];
#pragma unroll
            for (int f = 0; f < 6; f++) a += shW1[k * 6 + f] * feats[f];
            h[k] = tanhf(a);
        }
        float o = shB2;
#pragma unroll
        for (int k = 0; k < 12; k++) o += shW2[k] * h[k];
        out[batch] = 1.f / (1.f + expf(-o));
    }
}

extern "C" void kernel_launch(void* const* d_in, const int* in_sizes, int n_in,
                              void* d_out, int out_size) {
    const float* theta    = (const float*)d_in[0];
    const float* phi      = (const float*)d_in[1];
    const float* angles_x = (const float*)d_in[2];
    const float* angles_y = (const float*)d_in[3];
    const float* angles_z = (const float*)d_in[4];
    const float* u3_x     = (const float*)d_in[5];
    const float* u3_y     = (const float*)d_in[6];
    const float* u3_z     = (const float*)d_in[7];
    const float* W1       = (const float*)d_in[8];
    const float* b1       = (const float*)d_in[9];
    const float* W2       = (const float*)d_in[10];
    const float* b2       = (const float*)d_in[11];
    float* out = (float*)d_out;

    int B = in_sizes[0];
    int blocks = (B + 7) / 8;
    qcnn_kernel<<<blocks, 256>>>(theta, phi, angles_x, angles_y, angles_z,
                                 u3_x, u3_y, u3_z, W1, b1, W2, b2, out, B);
}